// round 12
// baseline (speedup 1.0000x reference)
#include <cuda_runtime.h>
#include <cuda_fp16.h>
#include <math.h>
#include <stdint.h>

#define B_DIM 4096
#define I_DIM 1024
#define O_DIM 1024
#define KTOT  4096            // 4 degree planes * 1024

// ---- scratch (static device globals: no allocation anywhere) ----
__device__ __half g_A[(size_t)B_DIM * KTOT];   // fp16 Chebyshev features [b][k']
__device__ __half g_W[(size_t)O_DIM * KTOT];   // fp16 coeffs transposed  [o][k']
__device__ float  g_bias_part[32][O_DIM];      // per-i-block partial sums of C[:,o,0]
__device__ float  g_bias[O_DIM];               // sum_i C[i,o,0]

// ================= helpers =================
__device__ __forceinline__ uint32_t smem_u32(const void* p) {
    uint32_t a;
    asm("{ .reg .u64 t; cvta.to.shared.u64 t, %1; cvt.u32.u64 %0, t; }"
        : "=r"(a) : "l"(p));
    return a;
}
__device__ __forceinline__ void ldsm4(uint32_t* r, uint32_t addr) {
    asm volatile("ldmatrix.sync.aligned.m8n8.x4.shared.b16 {%0,%1,%2,%3}, [%4];"
                 : "=r"(r[0]), "=r"(r[1]), "=r"(r[2]), "=r"(r[3]) : "r"(addr));
}
__device__ __forceinline__ void mma16816(float* c, const uint32_t* a,
                                         uint32_t b0, uint32_t b1) {
    asm volatile(
        "mma.sync.aligned.m16n8k16.row.col.f32.f16.f16.f32 "
        "{%0,%1,%2,%3}, {%4,%5,%6,%7}, {%8,%9}, {%0,%1,%2,%3};"
        : "+f"(c[0]), "+f"(c[1]), "+f"(c[2]), "+f"(c[3])
        : "r"(a[0]), "r"(a[1]), "r"(a[2]), "r"(a[3]), "r"(b0), "r"(b1));
}
__device__ __forceinline__ void cpasync16(uint32_t dst, const void* src) {
    asm volatile("cp.async.cg.shared.global [%0], [%1], 16;" :: "r"(dst), "l"(src));
}

// ================= kernel 1: LN + tanh + Chebyshev features (fp16) =========
__global__ void ln_feat_kernel(const float* __restrict__ x,
                               const float* __restrict__ w,
                               const float* __restrict__ b) {
    int row = blockIdx.x;
    int tid = threadIdx.x;                 // 256 threads, 4 elements each
    float4 v = ((const float4*)(x + (size_t)row * I_DIM))[tid];
    float s  = v.x + v.y + v.z + v.w;
    float ss = v.x * v.x + v.y * v.y + v.z * v.z + v.w * v.w;
    #pragma unroll
    for (int o = 16; o > 0; o >>= 1) {
        s  += __shfl_down_sync(0xffffffffu, s, o);
        ss += __shfl_down_sync(0xffffffffu, ss, o);
    }
    __shared__ float rs[8], rss[8];
    __shared__ float s_mu, s_rstd;
    int wid = tid >> 5, lid = tid & 31;
    if (lid == 0) { rs[wid] = s; rss[wid] = ss; }
    __syncthreads();
    if (tid == 0) {
        float ts = 0.f, tss = 0.f;
        #pragma unroll
        for (int i = 0; i < 8; i++) { ts += rs[i]; tss += rss[i]; }
        float mu  = ts * (1.0f / I_DIM);
        float var = tss * (1.0f / I_DIM) - mu * mu;
        s_mu = mu; s_rstd = rsqrtf(var + 1e-5f);
    }
    __syncthreads();
    float mu = s_mu, rstd = s_rstd;
    float4 wv = ((const float4*)w)[tid];
    float4 bv = ((const float4*)b)[tid];
    float h[4];
    h[0] = tanhf((v.x - mu) * rstd * wv.x + bv.x);
    h[1] = tanhf((v.y - mu) * rstd * wv.y + bv.y);
    h[2] = tanhf((v.z - mu) * rstd * wv.z + bv.z);
    h[3] = tanhf((v.w - mu) * rstd * wv.w + bv.w);

    float t[4][4];                         // [degree-1][element]
    #pragma unroll
    for (int j = 0; j < 4; j++) {
        float h2 = h[j] + h[j];
        t[0][j] = h[j];
        t[1][j] = h2 * h[j] - 1.f;
        t[2][j] = h2 * t[1][j] - h[j];
        t[3][j] = h2 * t[2][j] - t[1][j];
    }
    int i0 = tid * 4;
    #pragma unroll
    for (int d = 0; d < 4; d++) {
        __half2 p0 = __floats2half2_rn(t[d][0], t[d][1]);
        __half2 p1 = __floats2half2_rn(t[d][2], t[d][3]);
        size_t off = (size_t)row * KTOT + d * I_DIM + i0;
        uint2 pk;
        pk.x = *(uint32_t*)&p0;
        pk.y = *(uint32_t*)&p1;
        *(uint2*)&g_A[off] = pk;
    }
}

// ============ kernel 2: coeff transpose to fp16 + d0 partial sums ==========
__global__ void prep_w_kernel(const float* __restrict__ C) {
    __shared__ __align__(16) __half sh[4][32][36];
    __shared__ float sb[32][33];           // [c=o local][r=i local]
    int i0 = blockIdx.x * 32, o0 = blockIdx.y * 32;
    int tid = threadIdx.x;
    #pragma unroll
    for (int j = 0; j < 4; j++) {
        int p = tid + 256 * j;
        int r = p >> 5, c = p & 31;        // r = local i, c = local o
        const float* base = C + ((size_t)(i0 + r) * O_DIM + (o0 + c)) * 5;
        sb[c][r] = base[0];
        #pragma unroll
        for (int d = 0; d < 4; d++)
            sh[d][c][r] = __float2half_rn(base[d + 1]);
    }
    __syncthreads();
    int oc = tid >> 3, icb = (tid & 7) * 4;
    #pragma unroll
    for (int d = 0; d < 4; d++) {
        uint2 vh = *(const uint2*)&sh[d][oc][icb];
        size_t off = (size_t)(o0 + oc) * KTOT + d * I_DIM + i0 + icb;
        *(uint2*)&g_W[off] = vh;
    }
    if (tid < 32) {
        float s = 0.f;
        #pragma unroll
        for (int r = 0; r < 32; r++) s += sb[tid][r];
        g_bias_part[blockIdx.x][o0 + tid] = s;
    }
}

// ================= kernel 3: reduce bias partials (deterministic) ==========
__global__ void bias_reduce_kernel() {
    int o = blockIdx.x * 256 + threadIdx.x;
    float s = 0.f;
    #pragma unroll
    for (int k = 0; k < 32; k++) s += g_bias_part[k][o];
    g_bias[o] = s;
}

// ================= kernel 4: HMMA GEMM + bias + silu =================
// Block 128(M) x 256(N), 8 warps 2(m) x 4(n), warp tile 64x64; k-chunk 64,
// 3-stage cp.async pipeline, occupancy 1. Arithmetic intensity per smem byte
// raised 1.5x vs 64x32 warp tiles -> smem BW no longer binding.
#define BM 128
#define BN 256
#define BKC 64
#define NT (KTOT / BKC)         // 64
#define A_TILE (BM * 128)       // 16384 B
#define B_TILE (BN * 128)       // 32768 B
#define STAGE_BYTES (A_TILE + B_TILE)          // 49152
#define SMEM_TOTAL (2048 + 3 * STAGE_BYTES)    // 149504 B; occ 1

__global__ __launch_bounds__(256, 1) void cheby_mma_gemm(float* __restrict__ out) {
    extern __shared__ char smem[];
    float* bias_s = (float*)smem;          // 256 floats
    char* tiles = smem + 2048;             // stage s: A at s*STAGE, B at +A_TILE

    int tid = threadIdx.x, lane = tid & 31, wid = tid >> 5;
    int warp_m = wid >> 2, warp_n = wid & 3;     // 2 x 4
    int row0 = blockIdx.x * BM, col0 = blockIdx.y * BN;
    bias_s[tid] = g_bias[col0 + tid];

    // loader: A rows lr0+32j (j<4), B rows lr0+32j (j<8); swizzle offset
    // invariant under +32 rows -> smem offset = ldo0 + 4096*j
    int lr0 = tid >> 3, lc0 = tid & 7;
    int ldo0 = lr0 * 128 + ((lc0 ^ (lr0 & 7)) << 4);
    const __half* Asrc = g_A + (size_t)(row0 + lr0) * KTOT + lc0 * 8;
    const __half* Wsrc = g_W + (size_t)(col0 + lr0) * KTOT + lc0 * 8;

    float acc[4][8][4];
    #pragma unroll
    for (int mt = 0; mt < 4; mt++)
        #pragma unroll
        for (int nt = 0; nt < 8; nt++)
            #pragma unroll
            for (int q2 = 0; q2 < 4; q2++) acc[mt][nt][q2] = 0.f;

    // preload stages 0 and 1
    #pragma unroll
    for (int pre = 0; pre < 2; pre++) {
        uint32_t ad = smem_u32(tiles + pre * STAGE_BYTES) + ldo0;
        int kb = pre * BKC;
        #pragma unroll
        for (int j = 0; j < 4; j++)
            cpasync16(ad + 4096 * j, Asrc + kb + (size_t)j * (32 * KTOT));
        #pragma unroll
        for (int j = 0; j < 8; j++)
            cpasync16(ad + A_TILE + 4096 * j, Wsrc + kb + (size_t)j * (32 * KTOT));
        asm volatile("cp.async.commit_group;");
    }

    int q = lane >> 3, lr = lane & 7;
    int stage = 0;

    for (int t = 0; t < NT; t++) {
        if (t < NT - 1) asm volatile("cp.async.wait_group 1;");
        else            asm volatile("cp.async.wait_group 0;");
        __syncthreads();

        uint32_t abase = smem_u32(tiles + stage * STAGE_BYTES);
        uint32_t bbase = abase + A_TILE;

        #pragma unroll
        for (int s = 0; s < 4; s++) {
            uint32_t afr[4][4], bfr[4][4];
            #pragma unroll
            for (int mt = 0; mt < 4; mt++) {
                int r = warp_m * 64 + mt * 16 + lr + (q & 1) * 8;
                ldsm4(afr[mt], abase + r * 128 + (((2 * s + (q >> 1)) ^ (r & 7)) << 4));
            }
            #pragma unroll
            for (int p = 0; p < 4; p++) {
                int r = warp_n * 64 + p * 16 + lr + (q >> 1) * 8;
                ldsm4(bfr[p], bbase + r * 128 + (((2 * s + (q & 1)) ^ (r & 7)) << 4));
            }
            #pragma unroll
            for (int mt = 0; mt < 4; mt++) {
                #pragma unroll
                for (int nt = 0; nt < 8; nt++) {
                    int p = nt >> 1, e = (nt & 1) * 2;
                    mma16816(acc[mt][nt], afr[mt], bfr[p][e], bfr[p][e + 1]);
                }
            }
        }

        // issue loads for stage t+2 (lands during the next full iteration)
        if (t + 2 < NT) {
            uint32_t ad = smem_u32(tiles + ((stage + 2) % 3) * STAGE_BYTES) + ldo0;
            int kb = (t + 2) * BKC;
            #pragma unroll
            for (int j = 0; j < 4; j++)
                cpasync16(ad + 4096 * j, Asrc + kb + (size_t)j * (32 * KTOT));
            #pragma unroll
            for (int j = 0; j < 8; j++)
                cpasync16(ad + A_TILE + 4096 * j, Wsrc + kb + (size_t)j * (32 * KTOT));
            asm volatile("cp.async.commit_group;");
        } else {
            asm volatile("cp.async.commit_group;");
        }
        stage = (stage + 1) % 3;
    }

    // epilogue: bias + silu, direct stores
    int g = lane >> 2, tig = lane & 3;
    #pragma unroll
    for (int mt = 0; mt < 4; mt++) {
        int rg = row0 + warp_m * 64 + mt * 16 + g;
        #pragma unroll
        for (int nt = 0; nt < 8; nt++) {
            int cl = warp_n * 64 + nt * 8 + 2 * tig;
            float b0 = bias_s[cl], b1 = bias_s[cl + 1];
            float y0 = acc[mt][nt][0] + b0;
            float y1 = acc[mt][nt][1] + b1;
            float y2 = acc[mt][nt][2] + b0;
            float y3 = acc[mt][nt][3] + b1;
            float2 lo = make_float2(y0 * (1.f / (1.f + __expf(-y0))),
                                    y1 * (1.f / (1.f + __expf(-y1))));
            float2 hi = make_float2(y2 * (1.f / (1.f + __expf(-y2))),
                                    y3 * (1.f / (1.f + __expf(-y3))));
            *(float2*)(out + (size_t)rg * O_DIM + col0 + cl) = lo;
            *(float2*)(out + (size_t)(rg + 8) * O_DIM + col0 + cl) = hi;
        }
    }
}

// ================= launch =================
extern "C" void kernel_launch(void* const* d_in, const int* in_sizes, int n_in,
                              void* d_out, int out_size) {
    const float* x  = (const float*)d_in[0];   // [4096,1024]
    const float* C  = (const float*)d_in[1];   // [1024,1024,5]
    const float* w  = (const float*)d_in[2];   // [1024]
    const float* b  = (const float*)d_in[3];   // [1024]
    float* out = (float*)d_out;                // [4096,1024]

    cudaFuncSetAttribute(cheby_mma_gemm,
                         cudaFuncAttributeMaxDynamicSharedMemorySize, SMEM_TOTAL);

    ln_feat_kernel<<<B_DIM, 256>>>(x, w, b);
    prep_w_kernel<<<dim3(I_DIM / 32, O_DIM / 32), 256>>>(C);
    bias_reduce_kernel<<<O_DIM / 256, 256>>>();
    cheby_mma_gemm<<<dim3(B_DIM / BM, O_DIM / BN), 256, SMEM_TOTAL>>>(out);
}

// round 15
// speedup vs baseline: 1.0553x; 1.0553x over previous
#include <cuda_runtime.h>
#include <cuda_fp16.h>
#include <math.h>
#include <stdint.h>

#define B_DIM 4096
#define I_DIM 1024
#define O_DIM 1024
#define KTOT  4096            // 4 degree planes * 1024

// ---- scratch (static device globals: no allocation anywhere) ----
__device__ __half g_A[(size_t)B_DIM * KTOT];   // fp16 Chebyshev features [b][k']
__device__ __half g_W[(size_t)O_DIM * KTOT];   // fp16 coeffs transposed  [o][k']
__device__ float  g_bias_part[32][O_DIM];      // per-i-block partial sums of C[:,o,0]

// ================= helpers =================
__device__ __forceinline__ uint32_t smem_u32(const void* p) {
    uint32_t a;
    asm("{ .reg .u64 t; cvta.to.shared.u64 t, %1; cvt.u32.u64 %0, t; }"
        : "=r"(a) : "l"(p));
    return a;
}
__device__ __forceinline__ void ldsm4(uint32_t* r, uint32_t addr) {
    asm volatile("ldmatrix.sync.aligned.m8n8.x4.shared.b16 {%0,%1,%2,%3}, [%4];"
                 : "=r"(r[0]), "=r"(r[1]), "=r"(r[2]), "=r"(r[3]) : "r"(addr));
}
__device__ __forceinline__ void mma16816(float* c, const uint32_t* a,
                                         uint32_t b0, uint32_t b1) {
    asm volatile(
        "mma.sync.aligned.m16n8k16.row.col.f32.f16.f16.f32 "
        "{%0,%1,%2,%3}, {%4,%5,%6,%7}, {%8,%9}, {%0,%1,%2,%3};"
        : "+f"(c[0]), "+f"(c[1]), "+f"(c[2]), "+f"(c[3])
        : "r"(a[0]), "r"(a[1]), "r"(a[2]), "r"(a[3]), "r"(b0), "r"(b1));
}
__device__ __forceinline__ void cpasync16(uint32_t dst, const void* src) {
    asm volatile("cp.async.cg.shared.global [%0], [%1], 16;" :: "r"(dst), "l"(src));
}
__device__ __forceinline__ float tanh_fast(float x) {
    float y;
    asm("tanh.approx.f32 %0, %1;" : "=f"(y) : "f"(x));
    return y;
}

// ================= kernel 1: LN + tanh + Chebyshev features (fp16) =========
__global__ void ln_feat_kernel(const float* __restrict__ x,
                               const float* __restrict__ w,
                               const float* __restrict__ b) {
    int row = blockIdx.x;
    int tid = threadIdx.x;                 // 256 threads, 4 elements each
    float4 v = ((const float4*)(x + (size_t)row * I_DIM))[tid];
    float s  = v.x + v.y + v.z + v.w;
    float ss = v.x * v.x + v.y * v.y + v.z * v.z + v.w * v.w;
    #pragma unroll
    for (int o = 16; o > 0; o >>= 1) {
        s  += __shfl_down_sync(0xffffffffu, s, o);
        ss += __shfl_down_sync(0xffffffffu, ss, o);
    }
    __shared__ float rs[8], rss[8];
    __shared__ float s_mu, s_rstd;
    int wid = tid >> 5, lid = tid & 31;
    if (lid == 0) { rs[wid] = s; rss[wid] = ss; }
    __syncthreads();
    if (tid == 0) {
        float ts = 0.f, tss = 0.f;
        #pragma unroll
        for (int i = 0; i < 8; i++) { ts += rs[i]; tss += rss[i]; }
        float mu  = ts * (1.0f / I_DIM);
        float var = tss * (1.0f / I_DIM) - mu * mu;
        s_mu = mu; s_rstd = rsqrtf(var + 1e-5f);
    }
    __syncthreads();
    float mu = s_mu, rstd = s_rstd;
    float4 wv = ((const float4*)w)[tid];
    float4 bv = ((const float4*)b)[tid];
    float h[4];
    h[0] = tanh_fast((v.x - mu) * rstd * wv.x + bv.x);
    h[1] = tanh_fast((v.y - mu) * rstd * wv.y + bv.y);
    h[2] = tanh_fast((v.z - mu) * rstd * wv.z + bv.z);
    h[3] = tanh_fast((v.w - mu) * rstd * wv.w + bv.w);

    float t[4][4];                         // [degree-1][element]
    #pragma unroll
    for (int j = 0; j < 4; j++) {
        float h2 = h[j] + h[j];
        t[0][j] = h[j];
        t[1][j] = h2 * h[j] - 1.f;
        t[2][j] = h2 * t[1][j] - h[j];
        t[3][j] = h2 * t[2][j] - t[1][j];
    }
    int i0 = tid * 4;
    #pragma unroll
    for (int d = 0; d < 4; d++) {
        __half2 p0 = __floats2half2_rn(t[d][0], t[d][1]);
        __half2 p1 = __floats2half2_rn(t[d][2], t[d][3]);
        size_t off = (size_t)row * KTOT + d * I_DIM + i0;
        uint2 pk;
        pk.x = *(uint32_t*)&p0;
        pk.y = *(uint32_t*)&p1;
        *(uint2*)&g_A[off] = pk;
    }
}

// ============ kernel 2: coeff transpose to fp16 + d0 partial sums ==========
__global__ void prep_w_kernel(const float* __restrict__ C) {
    __shared__ __align__(16) __half sh[4][32][36];
    __shared__ float sb[32][33];           // [c=o local][r=i local]
    int i0 = blockIdx.x * 32, o0 = blockIdx.y * 32;
    int tid = threadIdx.x;
    #pragma unroll
    for (int j = 0; j < 4; j++) {
        int p = tid + 256 * j;
        int r = p >> 5, c = p & 31;        // r = local i, c = local o
        const float* base = C + ((size_t)(i0 + r) * O_DIM + (o0 + c)) * 5;
        sb[c][r] = base[0];
        #pragma unroll
        for (int d = 0; d < 4; d++)
            sh[d][c][r] = __float2half_rn(base[d + 1]);
    }
    __syncthreads();
    int oc = tid >> 3, icb = (tid & 7) * 4;
    #pragma unroll
    for (int d = 0; d < 4; d++) {
        uint2 vh = *(const uint2*)&sh[d][oc][icb];
        size_t off = (size_t)(o0 + oc) * KTOT + d * I_DIM + i0 + icb;
        *(uint2*)&g_W[off] = vh;
    }
    if (tid < 32) {
        float s = 0.f;
        #pragma unroll
        for (int r = 0; r < 32; r++) s += sb[tid][r];
        g_bias_part[blockIdx.x][o0 + tid] = s;
    }
}

// ================= kernel 3: HMMA GEMM + bias + silu =================
// Block 128x128, 8 warps 2(m) x 4(n), warp tile 64x32; k-chunk 64,
// 3-stage cp.async pipeline (R8 mainloop — best measured config).
// Bias reduction folded into the prologue, overlapped with cp.async preload.
#define BM 128
#define BN 128
#define BKC 64
#define NT (KTOT / BKC)         // 64
#define TILE_BYTES (128 * 128)  // one operand tile: 128 rows * 128B
#define STAGE_BYTES (2 * TILE_BYTES)
#define SMEM_TOTAL (1024 + 3 * STAGE_BYTES)   // 99328 B; 2 CTAs/SM

__global__ __launch_bounds__(256, 2) void cheby_mma_gemm(float* __restrict__ out) {
    extern __shared__ char smem[];
    float* bias_s = (float*)smem;
    char* tiles = smem + 1024;             // stage s: A at s*STAGE, B at +TILE

    int tid = threadIdx.x, lane = tid & 31, wid = tid >> 5;
    int warp_m = wid >> 2, warp_n = wid & 3;
    int row0 = blockIdx.x * BM, col0 = blockIdx.y * BN;

    // loader: slot j = base + 32j rows; swizzle offset is ldo0 + 4096j
    int lr0 = tid >> 3, lc0 = tid & 7;
    int ldo0 = lr0 * 128 + ((lc0 ^ (lr0 & 7)) << 4);
    const __half* Asrc = g_A + (size_t)(row0 + lr0) * KTOT + lc0 * 8;
    const __half* Wsrc = g_W + (size_t)(col0 + lr0) * KTOT + lc0 * 8;

    // preload stages 0 and 1
    #pragma unroll
    for (int pre = 0; pre < 2; pre++) {
        uint32_t ad = smem_u32(tiles + pre * STAGE_BYTES) + ldo0;
        int kb = pre * BKC;
        #pragma unroll
        for (int j = 0; j < 4; j++) {
            cpasync16(ad + 4096 * j,              Asrc + kb + (size_t)j * (32 * KTOT));
            cpasync16(ad + TILE_BYTES + 4096 * j, Wsrc + kb + (size_t)j * (32 * KTOT));
        }
        asm volatile("cp.async.commit_group;");
    }

    // bias reduction for this CTA's 128 columns (overlaps cp.async flight)
    if (tid < 128) {
        float s = 0.f;
        #pragma unroll
        for (int k = 0; k < 32; k++) s += g_bias_part[k][col0 + tid];
        bias_s[tid] = s;
    }

    float acc[4][4][4];
    #pragma unroll
    for (int mt = 0; mt < 4; mt++)
        #pragma unroll
        for (int nt = 0; nt < 4; nt++)
            #pragma unroll
            for (int q2 = 0; q2 < 4; q2++) acc[mt][nt][q2] = 0.f;

    int q = lane >> 3, lr = lane & 7;
    int stage = 0;

    for (int t = 0; t < NT; t++) {
        if (t < NT - 1) asm volatile("cp.async.wait_group 1;");
        else            asm volatile("cp.async.wait_group 0;");
        __syncthreads();

        uint32_t abase = smem_u32(tiles + stage * STAGE_BYTES);
        uint32_t bbase = abase + TILE_BYTES;

        #pragma unroll
        for (int s = 0; s < 4; s++) {
            uint32_t afr[4][4], bfr[2][4];
            #pragma unroll
            for (int mt = 0; mt < 4; mt++) {
                int r = warp_m * 64 + mt * 16 + lr + (q & 1) * 8;
                ldsm4(afr[mt], abase + r * 128 + (((2 * s + (q >> 1)) ^ (r & 7)) << 4));
            }
            #pragma unroll
            for (int p = 0; p < 2; p++) {
                int r = warp_n * 32 + p * 16 + lr + (q >> 1) * 8;
                ldsm4(bfr[p], bbase + r * 128 + (((2 * s + (q & 1)) ^ (r & 7)) << 4));
            }
            #pragma unroll
            for (int mt = 0; mt < 4; mt++) {
                #pragma unroll
                for (int nt = 0; nt < 4; nt++) {
                    int p = nt >> 1, e = (nt & 1) * 2;
                    mma16816(acc[mt][nt], afr[mt], bfr[p][e], bfr[p][e + 1]);
                }
            }
        }

        // issue loads for stage t+2 (lands during the next full iteration)
        if (t + 2 < NT) {
            uint32_t ad = smem_u32(tiles + ((stage + 2) % 3) * STAGE_BYTES) + ldo0;
            int kb = (t + 2) * BKC;
            #pragma unroll
            for (int j = 0; j < 4; j++) {
                cpasync16(ad + 4096 * j,              Asrc + kb + (size_t)j * (32 * KTOT));
                cpasync16(ad + TILE_BYTES + 4096 * j, Wsrc + kb + (size_t)j * (32 * KTOT));
            }
            asm volatile("cp.async.commit_group;");
        } else {
            asm volatile("cp.async.commit_group;");
        }
        stage = (stage + 1) % 3;
    }

    // epilogue: bias + silu, direct stores
    int g = lane >> 2, tig = lane & 3;
    #pragma unroll
    for (int mt = 0; mt < 4; mt++) {
        int rg = row0 + warp_m * 64 + mt * 16 + g;
        #pragma unroll
        for (int nt = 0; nt < 4; nt++) {
            int cl = warp_n * 32 + nt * 8 + 2 * tig;
            float b0 = bias_s[cl], b1 = bias_s[cl + 1];
            float y0 = acc[mt][nt][0] + b0;
            float y1 = acc[mt][nt][1] + b1;
            float y2 = acc[mt][nt][2] + b0;
            float y3 = acc[mt][nt][3] + b1;
            float2 lo = make_float2(y0 * (1.f / (1.f + __expf(-y0))),
                                    y1 * (1.f / (1.f + __expf(-y1))));
            float2 hi = make_float2(y2 * (1.f / (1.f + __expf(-y2))),
                                    y3 * (1.f / (1.f + __expf(-y3))));
            *(float2*)(out + (size_t)rg * O_DIM + col0 + cl) = lo;
            *(float2*)(out + (size_t)(rg + 8) * O_DIM + col0 + cl) = hi;
        }
    }
}

// ================= launch =================
extern "C" void kernel_launch(void* const* d_in, const int* in_sizes, int n_in,
                              void* d_out, int out_size) {
    const float* x  = (const float*)d_in[0];   // [4096,1024]
    const float* C  = (const float*)d_in[1];   // [1024,1024,5]
    const float* w  = (const float*)d_in[2];   // [1024]
    const float* b  = (const float*)d_in[3];   // [1024]
    float* out = (float*)d_out;                // [4096,1024]

    cudaFuncSetAttribute(cheby_mma_gemm,
                         cudaFuncAttributeMaxDynamicSharedMemorySize, SMEM_TOTAL);

    ln_feat_kernel<<<B_DIM, 256>>>(x, w, b);
    prep_w_kernel<<<dim3(I_DIM / 32, O_DIM / 32), 256>>>(C);
    cheby_mma_gemm<<<dim3(B_DIM / BM, O_DIM / BN), 256, SMEM_TOTAL>>>(out);
}

// round 17
// speedup vs baseline: 1.0957x; 1.0383x over previous
#include <cuda_runtime.h>
#include <cuda_fp16.h>
#include <math.h>
#include <stdint.h>

#define B_DIM 4096
#define I_DIM 1024
#define O_DIM 1024
#define KTOT  4096            // 4 degree planes * 1024

// ---- scratch (static device globals: no allocation anywhere) ----
__device__ __half g_A[(size_t)B_DIM * KTOT];   // fp16 Chebyshev features [b][k']
__device__ __half g_W[(size_t)O_DIM * KTOT];   // fp16 coeffs transposed  [o][k']
__device__ float  g_bias_part[32][O_DIM];      // per-i-block partial sums of C[:,o,0]

// ================= helpers =================
__device__ __forceinline__ uint32_t smem_u32(const void* p) {
    uint32_t a;
    asm("{ .reg .u64 t; cvta.to.shared.u64 t, %1; cvt.u32.u64 %0, t; }"
        : "=r"(a) : "l"(p));
    return a;
}
__device__ __forceinline__ void ldsm4(uint32_t* r, uint32_t addr) {
    asm volatile("ldmatrix.sync.aligned.m8n8.x4.shared.b16 {%0,%1,%2,%3}, [%4];"
                 : "=r"(r[0]), "=r"(r[1]), "=r"(r[2]), "=r"(r[3]) : "r"(addr));
}
__device__ __forceinline__ void mma16816(float* c, const uint32_t* a,
                                         uint32_t b0, uint32_t b1) {
    asm volatile(
        "mma.sync.aligned.m16n8k16.row.col.f32.f16.f16.f32 "
        "{%0,%1,%2,%3}, {%4,%5,%6,%7}, {%8,%9}, {%0,%1,%2,%3};"
        : "+f"(c[0]), "+f"(c[1]), "+f"(c[2]), "+f"(c[3])
        : "r"(a[0]), "r"(a[1]), "r"(a[2]), "r"(a[3]), "r"(b0), "r"(b1));
}
__device__ __forceinline__ void cpasync16(uint32_t dst, const void* src) {
    asm volatile("cp.async.cg.shared.global [%0], [%1], 16;" :: "r"(dst), "l"(src));
}
__device__ __forceinline__ float tanh_fast(float x) {
    float y;
    asm("tanh.approx.f32 %0, %1;" : "=f"(y) : "f"(x));
    return y;
}

// ====== fused prep: LN+tanh+Chebyshev rows AND coeff transpose, 4:1 ========
// grid = 5120 blocks of 256. bid%5==4 -> W block (wb=bid/5, 1024 of them);
// else LN row block (row = (bid/5)*4 + bid%5, 4096 of them). Interleaving
// keeps both memory streams co-resident on every SM for the whole launch.
__global__ void fused_prep_kernel(const float* __restrict__ x,
                                  const float* __restrict__ w,
                                  const float* __restrict__ b,
                                  const float* __restrict__ C) {
    __shared__ __align__(16) char su[13440];
    int bid = blockIdx.x;
    int tid = threadIdx.x;

    if ((bid % 5) == 4) {
        // ---------- W-transpose + d0 partial sums (32x32 i,o tile) ----------
        __half (*sh)[32][36] = (__half(*)[32][36])su;          // 9216 B
        float  (*sb)[33]     = (float(*)[33])(su + 9216);      // 4224 B
        int wb = bid / 5;
        int i0 = (wb & 31) * 32, o0 = (wb >> 5) * 32;
        #pragma unroll
        for (int j = 0; j < 4; j++) {
            int p = tid + 256 * j;
            int r = p >> 5, c = p & 31;    // r = local i, c = local o
            const float* base = C + ((size_t)(i0 + r) * O_DIM + (o0 + c)) * 5;
            sb[c][r] = base[0];
            #pragma unroll
            for (int d = 0; d < 4; d++)
                sh[d][c][r] = __float2half_rn(base[d + 1]);
        }
        __syncthreads();
        int oc = tid >> 3, icb = (tid & 7) * 4;
        #pragma unroll
        for (int d = 0; d < 4; d++) {
            uint2 vh = *(const uint2*)&sh[d][oc][icb];
            size_t off = (size_t)(o0 + oc) * KTOT + d * I_DIM + i0 + icb;
            *(uint2*)&g_W[off] = vh;
        }
        if (tid < 32) {
            float s = 0.f;
            #pragma unroll
            for (int r = 0; r < 32; r++) s += sb[tid][r];
            g_bias_part[i0 >> 5][o0 + tid] = s;
        }
    } else {
        // ---------- LN + tanh + Chebyshev features for one row ----------
        float* rs  = (float*)su;            // 8 floats
        float* rss = (float*)su + 8;        // 8 floats
        int row = (bid / 5) * 4 + (bid % 5);
        float4 v = ((const float4*)(x + (size_t)row * I_DIM))[tid];
        float s  = v.x + v.y + v.z + v.w;
        float ss = v.x * v.x + v.y * v.y + v.z * v.z + v.w * v.w;
        #pragma unroll
        for (int o = 16; o > 0; o >>= 1) {
            s  += __shfl_down_sync(0xffffffffu, s, o);
            ss += __shfl_down_sync(0xffffffffu, ss, o);
        }
        int wid = tid >> 5, lid = tid & 31;
        if (lid == 0) { rs[wid] = s; rss[wid] = ss; }
        __syncthreads();
        // every thread reduces the 8 partials (no second barrier needed)
        float ts = 0.f, tss = 0.f;
        #pragma unroll
        for (int i = 0; i < 8; i++) { ts += rs[i]; tss += rss[i]; }
        float mu   = ts * (1.0f / I_DIM);
        float var  = tss * (1.0f / I_DIM) - mu * mu;
        float rstd = rsqrtf(var + 1e-5f);

        float4 wv = ((const float4*)w)[tid];
        float4 bv = ((const float4*)b)[tid];
        float h[4];
        h[0] = tanh_fast((v.x - mu) * rstd * wv.x + bv.x);
        h[1] = tanh_fast((v.y - mu) * rstd * wv.y + bv.y);
        h[2] = tanh_fast((v.z - mu) * rstd * wv.z + bv.z);
        h[3] = tanh_fast((v.w - mu) * rstd * wv.w + bv.w);

        float t[4][4];                     // [degree-1][element]
        #pragma unroll
        for (int j = 0; j < 4; j++) {
            float h2 = h[j] + h[j];
            t[0][j] = h[j];
            t[1][j] = h2 * h[j] - 1.f;
            t[2][j] = h2 * t[1][j] - h[j];
            t[3][j] = h2 * t[2][j] - t[1][j];
        }
        int i0 = tid * 4;
        #pragma unroll
        for (int d = 0; d < 4; d++) {
            __half2 p0 = __floats2half2_rn(t[d][0], t[d][1]);
            __half2 p1 = __floats2half2_rn(t[d][2], t[d][3]);
            size_t off = (size_t)row * KTOT + d * I_DIM + i0;
            uint2 pk;
            pk.x = *(uint32_t*)&p0;
            pk.y = *(uint32_t*)&p1;
            *(uint2*)&g_A[off] = pk;
        }
    }
}

// ================= kernel 2: HMMA GEMM + bias + silu =================
// Block 128x128, 8 warps 2(m) x 4(n), warp tile 64x32; k-chunk 64,
// 3-stage cp.async pipeline (R8 mainloop — best measured config).
// Bias reduction folded into the prologue, overlapped with cp.async preload.
#define BM 128
#define BN 128
#define BKC 64
#define NT (KTOT / BKC)         // 64
#define TILE_BYTES (128 * 128)  // one operand tile: 128 rows * 128B
#define STAGE_BYTES (2 * TILE_BYTES)
#define SMEM_TOTAL (1024 + 3 * STAGE_BYTES)   // 99328 B; 2 CTAs/SM

__global__ __launch_bounds__(256, 2) void cheby_mma_gemm(float* __restrict__ out) {
    extern __shared__ char smem[];
    float* bias_s = (float*)smem;
    char* tiles = smem + 1024;             // stage s: A at s*STAGE, B at +TILE

    int tid = threadIdx.x, lane = tid & 31, wid = tid >> 5;
    int warp_m = wid >> 2, warp_n = wid & 3;
    int row0 = blockIdx.x * BM, col0 = blockIdx.y * BN;

    // loader: slot j = base + 32j rows; swizzle offset is ldo0 + 4096j
    int lr0 = tid >> 3, lc0 = tid & 7;
    int ldo0 = lr0 * 128 + ((lc0 ^ (lr0 & 7)) << 4);
    const __half* Asrc = g_A + (size_t)(row0 + lr0) * KTOT + lc0 * 8;
    const __half* Wsrc = g_W + (size_t)(col0 + lr0) * KTOT + lc0 * 8;

    // preload stages 0 and 1
    #pragma unroll
    for (int pre = 0; pre < 2; pre++) {
        uint32_t ad = smem_u32(tiles + pre * STAGE_BYTES) + ldo0;
        int kb = pre * BKC;
        #pragma unroll
        for (int j = 0; j < 4; j++) {
            cpasync16(ad + 4096 * j,              Asrc + kb + (size_t)j * (32 * KTOT));
            cpasync16(ad + TILE_BYTES + 4096 * j, Wsrc + kb + (size_t)j * (32 * KTOT));
        }
        asm volatile("cp.async.commit_group;");
    }

    // bias reduction for this CTA's 128 columns (overlaps cp.async flight)
    if (tid < 128) {
        float s = 0.f;
        #pragma unroll
        for (int k = 0; k < 32; k++) s += g_bias_part[k][col0 + tid];
        bias_s[tid] = s;
    }

    float acc[4][4][4];
    #pragma unroll
    for (int mt = 0; mt < 4; mt++)
        #pragma unroll
        for (int nt = 0; nt < 4; nt++)
            #pragma unroll
            for (int q2 = 0; q2 < 4; q2++) acc[mt][nt][q2] = 0.f;

    int q = lane >> 3, lr = lane & 7;
    int stage = 0;

    for (int t = 0; t < NT; t++) {
        if (t < NT - 1) asm volatile("cp.async.wait_group 1;");
        else            asm volatile("cp.async.wait_group 0;");
        __syncthreads();

        uint32_t abase = smem_u32(tiles + stage * STAGE_BYTES);
        uint32_t bbase = abase + TILE_BYTES;

        #pragma unroll
        for (int s = 0; s < 4; s++) {
            uint32_t afr[4][4], bfr[2][4];
            #pragma unroll
            for (int mt = 0; mt < 4; mt++) {
                int r = warp_m * 64 + mt * 16 + lr + (q & 1) * 8;
                ldsm4(afr[mt], abase + r * 128 + (((2 * s + (q >> 1)) ^ (r & 7)) << 4));
            }
            #pragma unroll
            for (int p = 0; p < 2; p++) {
                int r = warp_n * 32 + p * 16 + lr + (q >> 1) * 8;
                ldsm4(bfr[p], bbase + r * 128 + (((2 * s + (q & 1)) ^ (r & 7)) << 4));
            }
            #pragma unroll
            for (int mt = 0; mt < 4; mt++) {
                #pragma unroll
                for (int nt = 0; nt < 4; nt++) {
                    int p = nt >> 1, e = (nt & 1) * 2;
                    mma16816(acc[mt][nt], afr[mt], bfr[p][e], bfr[p][e + 1]);
                }
            }
        }

        // issue loads for stage t+2 (lands during the next full iteration)
        if (t + 2 < NT) {
            uint32_t ad = smem_u32(tiles + ((stage + 2) % 3) * STAGE_BYTES) + ldo0;
            int kb = (t + 2) * BKC;
            #pragma unroll
            for (int j = 0; j < 4; j++) {
                cpasync16(ad + 4096 * j,              Asrc + kb + (size_t)j * (32 * KTOT));
                cpasync16(ad + TILE_BYTES + 4096 * j, Wsrc + kb + (size_t)j * (32 * KTOT));
            }
            asm volatile("cp.async.commit_group;");
        } else {
            asm volatile("cp.async.commit_group;");
        }
        stage = (stage + 1) % 3;
    }

    // epilogue: bias + silu, direct stores
    int g = lane >> 2, tig = lane & 3;
    #pragma unroll
    for (int mt = 0; mt < 4; mt++) {
        int rg = row0 + warp_m * 64 + mt * 16 + g;
        #pragma unroll
        for (int nt = 0; nt < 4; nt++) {
            int cl = warp_n * 32 + nt * 8 + 2 * tig;
            float b0 = bias_s[cl], b1 = bias_s[cl + 1];
            float y0 = acc[mt][nt][0] + b0;
            float y1 = acc[mt][nt][1] + b1;
            float y2 = acc[mt][nt][2] + b0;
            float y3 = acc[mt][nt][3] + b1;
            float2 lo = make_float2(y0 * (1.f / (1.f + __expf(-y0))),
                                    y1 * (1.f / (1.f + __expf(-y1))));
            float2 hi = make_float2(y2 * (1.f / (1.f + __expf(-y2))),
                                    y3 * (1.f / (1.f + __expf(-y3))));
            *(float2*)(out + (size_t)rg * O_DIM + col0 + cl) = lo;
            *(float2*)(out + (size_t)(rg + 8) * O_DIM + col0 + cl) = hi;
        }
    }
}

// ================= launch =================
extern "C" void kernel_launch(void* const* d_in, const int* in_sizes, int n_in,
                              void* d_out, int out_size) {
    const float* x  = (const float*)d_in[0];   // [4096,1024]
    const float* C  = (const float*)d_in[1];   // [1024,1024,5]
    const float* w  = (const float*)d_in[2];   // [1024]
    const float* b  = (const float*)d_in[3];   // [1024]
    float* out = (float*)d_out;                // [4096,1024]

    cudaFuncSetAttribute(cheby_mma_gemm,
                         cudaFuncAttributeMaxDynamicSharedMemorySize, SMEM_TOTAL);

    fused_prep_kernel<<<5120, 256>>>(x, w, b, C);
    cheby_mma_gemm<<<dim3(B_DIM / BM, O_DIM / BN), 256, SMEM_TOTAL>>>(out);
}